// round 1
// baseline (speedup 1.0000x reference)
#include <cuda_runtime.h>
#include <math.h>

#define EPSC 1e-5f

// ---- scratch (no allocation allowed) ----
__device__ float g_feats[4096 * 64];      // 3072 support + 1024 query features
__device__ float g_lors[512 * 24 * 64];   // (B, S*4, DIM)
__device__ float g_ploss[128];
__device__ float g_pcorr[128];

__device__ __forceinline__ float gelu_f(float x) {
    return 0.5f * x * (1.0f + erff(x * 0.70710678118654752f));
}

// =====================================================================
// Kernel 1: per-image feature extractor
//   conv1(1->32,3x3,pad1) -> bn1 -> pool(28->8, 4x4 avg windows) -> gelu
//   conv2(32->32) -> bn2 -> gelu ; conv3 -> bn3 -> gelu
//   conv4(32->1) -> bn4 -> gelu ; flatten -> @ lin_w^T
// One block per image, 512 threads. conv1+pool fused via integral image.
// =====================================================================

__device__ __forceinline__ void conv3x3_32(
    const float* __restrict__ src, float* __restrict__ dst,
    const float* __restrict__ ws,      // [(ci*9+k)*32 + co]
    const float* __restrict__ A, const float* __restrict__ Bv,
    int c, int yy, int xx0)
{
    float a0 = 0.f, a1 = 0.f, a2 = 0.f, a3 = 0.f;
#pragma unroll
    for (int dy = 0; dy < 3; dy++) {
        const float* rowp = src + ((yy + dy) * 10 + xx0) * 32;
        const float* wb = ws + (dy * 3) * 32 + c;
#pragma unroll 8
        for (int ci = 0; ci < 32; ci++) {
            float v0 = rowp[ci];
            float v1 = rowp[ci + 32];
            float v2 = rowp[ci + 64];
            float v3 = rowp[ci + 96];
            float v4 = rowp[ci + 128];
            float v5 = rowp[ci + 160];
            const float* wp = wb + ci * 288;
            float wa = wp[0], wbv = wp[32], wc = wp[64];
            a0 = fmaf(v0, wa, fmaf(v1, wbv, fmaf(v2, wc, a0)));
            a1 = fmaf(v1, wa, fmaf(v2, wbv, fmaf(v3, wc, a1)));
            a2 = fmaf(v2, wa, fmaf(v3, wbv, fmaf(v4, wc, a2)));
            a3 = fmaf(v3, wa, fmaf(v4, wbv, fmaf(v5, wc, a3)));
        }
    }
    float Ac = A[c], Bc = Bv[c];
    dst[((yy + 1) * 10 + (xx0 + 1)) * 32 + c] = gelu_f(a0 * Ac + Bc);
    dst[((yy + 1) * 10 + (xx0 + 2)) * 32 + c] = gelu_f(a1 * Ac + Bc);
    dst[((yy + 1) * 10 + (xx0 + 3)) * 32 + c] = gelu_f(a2 * Ac + Bc);
    dst[((yy + 1) * 10 + (xx0 + 4)) * 32 + c] = gelu_f(a3 * Ac + Bc);
}

__global__ __launch_bounds__(512, 1) void feat_kernel(
    const float* __restrict__ sxs, const float* __restrict__ qxs,
    const float* __restrict__ c1w, const float* __restrict__ c1b, const float* __restrict__ bn1,
    const float* __restrict__ c2w, const float* __restrict__ c2b, const float* __restrict__ bn2,
    const float* __restrict__ c3w, const float* __restrict__ c3b, const float* __restrict__ bn3,
    const float* __restrict__ c4w, const float* __restrict__ c4b, const float* __restrict__ bn4,
    const float* __restrict__ lin_w)
{
    extern __shared__ float sm[];
    float* inpad = sm;               // 900  (30x30 zero-padded image)
    float* I     = sm + 900;         // 992  (31x31 integral image, stride 32)
    float* Wsum  = I + 992;          // 576  (24x24 4x4 box sums)
    float* w1s   = Wsum + 576;       // 288  [k*32+co]
    float* A1    = w1s + 288;        // 32
    float* B1v   = A1 + 32;          // 32
    float* A2    = B1v + 32;         // 32
    float* B2v   = A2 + 32;          // 32
    float* A3    = B2v + 32;         // 32
    float* B3v   = A3 + 32;          // 32
    float* AB4   = B3v + 32;         // 2
    float* w2s   = AB4 + 2;          // 9216 [(ci*9+k)*32+co]
    float* w3s   = w2s + 9216;       // 9216
    float* w4s   = w3s + 9216;       // 288  [ci*9+k]
    float* linT  = w4s + 288;        // 4160 [j*65+e]
    float* buf0  = linT + 4160;      // 3200 (10x10x32, zero pad ring)
    float* buf1  = buf0 + 3200;      // 3200
    float* flat  = buf1 + 3200;      // 64

    const int t = threadIdx.x;
    const int img = blockIdx.x;
    const float* src = (img < 3072) ? (sxs + img * 784) : (qxs + (img - 3072) * 784);

    for (int i = t; i < 900; i += 512) inpad[i] = 0.f;
    for (int i = t; i < 3200; i += 512) { buf0[i] = 0.f; buf1[i] = 0.f; }
    for (int i = t; i < 288; i += 512) {
        int co = i / 9, k = i % 9;
        w1s[k * 32 + co] = c1w[i];
        w4s[i] = c4w[i];                       // (1,32,3,3): i = ci*9+k
    }
    for (int i = t; i < 9216; i += 512) {
        int co = i / 288, ci = (i / 9) % 32, k = i % 9;
        int d = (ci * 9 + k) * 32 + co;
        w2s[d] = c2w[i];
        w3s[d] = c3w[i];
    }
    for (int i = t; i < 4096; i += 512) {
        int e = i >> 6, j = i & 63;
        linT[j * 65 + e] = lin_w[i];
    }
    if (t < 32) {
        float g = bn1[t], bt = bn1[32 + t], m = bn1[64 + t], v = bn1[96 + t];
        float sc = g * rsqrtf(v + EPSC);
        A1[t] = sc * (1.f / 16.f);
        B1v[t] = (c1b[t] - m) * sc + bt;
        g = bn2[t]; bt = bn2[32 + t]; m = bn2[64 + t]; v = bn2[96 + t];
        sc = g * rsqrtf(v + EPSC);
        A2[t] = sc; B2v[t] = (c2b[t] - m) * sc + bt;
        g = bn3[t]; bt = bn3[32 + t]; m = bn3[64 + t]; v = bn3[96 + t];
        sc = g * rsqrtf(v + EPSC);
        A3[t] = sc; B3v[t] = (c3b[t] - m) * sc + bt;
    }
    if (t == 0) {
        float g = bn4[0], bt = bn4[1], m = bn4[2], v = bn4[3];
        float sc = g * rsqrtf(v + EPSC);
        AB4[0] = sc; AB4[1] = (c4b[0] - m) * sc + bt;
    }
    for (int i = t; i < 31; i += 512) { I[i] = 0.f; I[i * 32] = 0.f; }
    __syncthreads();

    for (int i = t; i < 784; i += 512) {
        int y = i / 28, x = i % 28;
        inpad[(y + 1) * 30 + (x + 1)] = src[i];
    }
    __syncthreads();

    // integral image: row cumsum then col cumsum
    if (t < 30) {
        float run = 0.f;
        for (int j = 0; j < 30; j++) {
            run += inpad[t * 30 + j];
            I[(t + 1) * 32 + (j + 1)] = run;
        }
    }
    __syncthreads();
    if (t < 30) {
        float run = 0.f;
        int cc = t + 1;
        for (int i = 1; i <= 30; i++) { run += I[i * 32 + cc]; I[i * 32 + cc] = run; }
    }
    __syncthreads();

    // 4x4 box sums at positions (SO[o]+dy-1, SO[p]+dx-1)  (padded coords)
    {
        const int SO[8] = {0, 3, 7, 10, 14, 17, 21, 24};
        for (int i = t; i < 576; i += 512) {
            int a3 = i / 24, b3 = i % 24;
            int a = SO[a3 / 3] + (a3 % 3);
            int bb = SO[b3 / 3] + (b3 % 3);
            Wsum[i] = I[(a + 4) * 32 + (bb + 4)] - I[a * 32 + (bb + 4)]
                    - I[(a + 4) * 32 + bb] + I[a * 32 + bb];
        }
    }
    __syncthreads();

    const int c = t & 31;
    const int g = t >> 5;            // 0..15
    const int yy = g >> 1;           // output row 0..7
    const int xx0 = (g & 1) * 4;     // output col base 0 or 4

    // conv1 + pool + bn1 + gelu  (9 FMA per output cell via box sums)
    {
        float acc[4] = {0.f, 0.f, 0.f, 0.f};
#pragma unroll
        for (int dy = 0; dy < 3; dy++)
#pragma unroll
            for (int dx = 0; dx < 3; dx++) {
                float wv = w1s[(dy * 3 + dx) * 32 + c];
#pragma unroll
                for (int r = 0; r < 4; r++)
                    acc[r] = fmaf(wv, Wsum[(3 * yy + dy) * 24 + 3 * (xx0 + r) + dx], acc[r]);
            }
        float a1 = A1[c], b1v = B1v[c];
#pragma unroll
        for (int r = 0; r < 4; r++)
            buf0[((yy + 1) * 10 + (xx0 + r + 1)) * 32 + c] = gelu_f(acc[r] * a1 + b1v);
    }
    __syncthreads();

    conv3x3_32(buf0, buf1, w2s, A2, B2v, c, yy, xx0);   // conv2
    __syncthreads();
    conv3x3_32(buf1, buf0, w3s, A3, B3v, c, yy, xx0);   // conv3
    __syncthreads();

    // conv4: lane = ci, warp covers 4 cells; warp-reduce over ci
    {
        float acc[4] = {0.f, 0.f, 0.f, 0.f};
#pragma unroll
        for (int dy = 0; dy < 3; dy++)
#pragma unroll
            for (int dx = 0; dx < 3; dx++) {
                float wv = w4s[c * 9 + dy * 3 + dx];
#pragma unroll
                for (int r = 0; r < 4; r++)
                    acc[r] = fmaf(wv, buf0[((yy + dy) * 10 + (xx0 + r + dx)) * 32 + c], acc[r]);
            }
#pragma unroll
        for (int r = 0; r < 4; r++) {
            float v = acc[r];
            for (int o = 16; o; o >>= 1) v += __shfl_xor_sync(0xffffffffu, v, o);
            if (c == 0) flat[yy * 8 + xx0 + r] = gelu_f(v * AB4[0] + AB4[1]);
        }
    }
    __syncthreads();

    // linear: feat[e] = sum_j flat[j] * lin_w[e][j]
    if (t < 64) {
        float f = 0.f;
#pragma unroll 8
        for (int j = 0; j < 64; j++) f = fmaf(flat[j], linT[j * 65 + t], f);
        g_feats[img * 64 + t] = f;
    }
}

// =====================================================================
// Kernel 2: LoR adapter on support tokens (B*S*4 = 12288 tokens)
// 8 tokens per block x 64 threads = 512 threads
// =====================================================================
__global__ __launch_bounds__(512) void lor_kernel(
    const float* __restrict__ emb, const float* __restrict__ w1, const float* __restrict__ w2,
    const float* __restrict__ tags, const float* __restrict__ rq, const float* __restrict__ rk,
    const float* __restrict__ rv, const float* __restrict__ ro,
    const float* __restrict__ lnw, const float* __restrict__ lnb,
    const int* __restrict__ sys)
{
    extern __shared__ float sm[];
    float* w1T = sm;             // 4160 [d*65+e]
    float* w2T = w1T + 4160;     // 4160
    float* rqT = w2T + 4160;     // 4160 [d*65+j]
    float* roS = rqT + 4160;     // 4096 [d*64+e]
    float* rkT = roS + 4096;     // 1024 [(n*16+h)*16+r]
    float* rvS = rkT + 1024;     // 1024 [(r*4+n)*16+h]
    float* xs  = rvS + 1024;     // 512
    float* ahs = xs + 512;       // 512
    float* qvs = ahs + 512;      // 512
    float* lvs = qvs + 512;      // 512
    float* redA = lvs + 512;     // 16
    float* redB = redA + 16;     // 16

    const int t = threadIdx.x;
    for (int i = t; i < 4096; i += 512) {
        int e = i >> 6, d = i & 63;
        w1T[d * 65 + e] = w1[i];
        w2T[d * 65 + e] = w2[i];
        rqT[d * 65 + e] = rq[i];
        roS[i] = ro[i];
    }
    for (int i = t; i < 1024; i += 512) {
        int n = i >> 8, h = (i >> 4) & 15, r = i & 15;
        rkT[i] = rk[(r * 4 + n) * 16 + h];
        rvS[i] = rv[i];
    }
    __syncthreads();

    const int lt = t >> 6;
    const int j = t & 63;
    const int token = blockIdx.x * 8 + lt;
    const int b = token / 24;
    const int k24 = token - b * 24;
    const int s = k24 >> 2;
    const int tg = k24 & 3;

    int cls = sys[b * 6 + s];
    float xv = g_feats[(b * 6 + s) * 64 + j] + emb[cls * 64 + j] + tags[tg * 64 + j];
    xs[t] = xv;
    __syncthreads();

    float h1 = 0.f;
#pragma unroll 8
    for (int d = 0; d < 64; d++) h1 = fmaf(w1T[d * 65 + j], xs[lt * 64 + d], h1);
    ahs[t] = gelu_f(h1);
    __syncthreads();

    float qv = 0.f;
#pragma unroll 8
    for (int d = 0; d < 64; d++) qv = fmaf(w2T[d * 65 + j], ahs[lt * 64 + d], qv);
    qvs[t] = qv;
    __syncthreads();

    float qh = 0.f;
#pragma unroll 8
    for (int d = 0; d < 64; d++) qh = fmaf(rqT[d * 65 + j], qvs[lt * 64 + d], qh);

    const int n = j >> 4;
    const int sub = j & 15;
    float scv = 0.f;
#pragma unroll
    for (int hh = 0; hh < 16; hh++) {
        float qhh = __shfl_sync(0xffffffffu, qh, hh, 16);
        scv = fmaf(qhh, rkT[(n * 16 + hh) * 16 + sub], scv);
    }
    scv *= 0.25f;
    float mx = scv;
    for (int o = 8; o; o >>= 1) mx = fmaxf(mx, __shfl_xor_sync(0xffffffffu, mx, o, 16));
    float ee = expf(scv - mx);
    float ssum = ee;
    for (int o = 8; o; o >>= 1) ssum += __shfl_xor_sync(0xffffffffu, ssum, o, 16);
    float p = ee / ssum;

    float lv = 0.f;
#pragma unroll
    for (int r = 0; r < 16; r++) {
        float pr = __shfl_sync(0xffffffffu, p, r, 16);
        lv = fmaf(pr, rvS[(r * 4 + n) * 16 + sub], lv);
    }
    lvs[t] = lv;
    __syncthreads();

    float outv = 0.f;
#pragma unroll 8
    for (int d = 0; d < 64; d++) outv = fmaf(roS[d * 64 + j], lvs[lt * 64 + d], outv);
    float z = outv + xs[t];

    // layernorm over 64 (2 warps)
    float sv = z;
    for (int o = 16; o; o >>= 1) sv += __shfl_xor_sync(0xffffffffu, sv, o);
    int wh = (j >> 5);
    if ((j & 31) == 0) redA[lt * 2 + wh] = sv;
    __syncthreads();
    float mean = (redA[lt * 2] + redA[lt * 2 + 1]) * (1.f / 64.f);
    float dz = z - mean;
    float v2 = dz * dz;
    for (int o = 16; o; o >>= 1) v2 += __shfl_xor_sync(0xffffffffu, v2, o);
    if ((j & 31) == 0) redB[lt * 2 + wh] = v2;
    __syncthreads();
    float var = (redB[lt * 2] + redB[lt * 2 + 1]) * (1.f / 64.f);

    g_lors[token * 64 + j] = dz * rsqrtf(var + EPSC) * lnw[j] + lnb[j];
}

// =====================================================================
// Kernel 3: query path. 4 batch elements per block x 64 threads = 256.
// Rank-6 updated weights applied implicitly (never materialize qw1/qw2).
// =====================================================================
__global__ __launch_bounds__(256) void query_kernel(
    const float* __restrict__ emb, const float* __restrict__ w1, const float* __restrict__ w2,
    const float* __restrict__ tags, const int* __restrict__ qys)
{
    extern __shared__ float sm[];
    float* w1T = sm;             // 4160
    float* w2T = w1T + 4160;     // 4160
    float* lorS = w2T + 4160;    // 6144 (4 x 6x4x64)
    float* xq = lorS + 6144;     // 512
    float* ah = xq + 512;        // 512
    float* pd = ah + 512;        // 512
    float* d1 = pd + 512;        // 48
    float* d2 = d1 + 48;         // 48
    float* lg = d2 + 48;         // 16
    float* ls = lg + 16;         // 8
    float* cr = ls + 8;          // 8

    const int t = threadIdx.x;
    for (int i = t; i < 4096; i += 256) {
        int e = i >> 6, d = i & 63;
        w1T[d * 65 + e] = w1[i];
        w2T[d * 65 + e] = w2[i];
    }
    for (int i = t; i < 6144; i += 256) lorS[i] = g_lors[blockIdx.x * 6144 + i];

    const int bl = t >> 6;
    const int e = t & 63;
    const int b = blockIdx.x * 4 + bl;
    for (int q = 0; q < 2; q++)
        xq[(bl * 2 + q) * 64 + e] = g_feats[3072 * 64 + (b * 2 + q) * 64 + e] + tags[4 * 64 + e];
    __syncthreads();

    if (e < 12) {
        int s = e >> 1, q = e & 1;
        const float* r1 = lorS + bl * 1536 + (s * 4 + 1) * 64;
        const float* xx = xq + (bl * 2 + q) * 64;
        float acc = 0.f;
#pragma unroll 8
        for (int d = 0; d < 64; d++) acc = fmaf(r1[d], xx[d], acc);
        d1[bl * 12 + e] = acc;
    }
    __syncthreads();

    for (int q = 0; q < 2; q++) {
        const float* xx = xq + (bl * 2 + q) * 64;
        float acc = 0.f;
#pragma unroll 8
        for (int d = 0; d < 64; d++) acc = fmaf(w1T[d * 65 + e], xx[d], acc);
#pragma unroll
        for (int s = 0; s < 6; s++)
            acc = fmaf(lorS[bl * 1536 + (s * 4 + 0) * 64 + e], d1[bl * 12 + s * 2 + q], acc);
        ah[(bl * 2 + q) * 64 + e] = gelu_f(acc);
    }
    __syncthreads();

    if (e < 12) {
        int s = e >> 1, q = e & 1;
        const float* r2 = lorS + bl * 1536 + (s * 4 + 3) * 64;
        const float* aa = ah + (bl * 2 + q) * 64;
        float acc = 0.f;
#pragma unroll 8
        for (int d = 0; d < 64; d++) acc = fmaf(r2[d], aa[d], acc);
        d2[bl * 12 + e] = acc;
    }
    __syncthreads();

    for (int q = 0; q < 2; q++) {
        const float* aa = ah + (bl * 2 + q) * 64;
        float acc = 0.f;
#pragma unroll 8
        for (int d = 0; d < 64; d++) acc = fmaf(w2T[d * 65 + e], aa[d], acc);
#pragma unroll
        for (int s = 0; s < 6; s++)
            acc = fmaf(lorS[bl * 1536 + (s * 4 + 2) * 64 + e], d2[bl * 12 + s * 2 + q], acc);
        pd[(bl * 2 + q) * 64 + e] = acc;
    }
    __syncthreads();

    if (e < 4) {
        int q = e >> 1, l = e & 1;
        float acc = 0.f;
#pragma unroll 8
        for (int d = 0; d < 64; d++) acc = fmaf(emb[l * 64 + d], pd[(bl * 2 + q) * 64 + d], acc);
        lg[bl * 4 + e] = acc;
    }
    __syncthreads();

    if (e < 2) {
        int q = e;
        float l0 = lg[bl * 4 + q * 2], l1 = lg[bl * 4 + q * 2 + 1];
        int y = qys[b * 2 + q];
        float m = fmaxf(l0, l1);
        float lse = m + logf(expf(l0 - m) + expf(l1 - m));
        ls[bl * 2 + q] = lse - (y ? l1 : l0);
        int pred = (l1 > l0) ? 1 : 0;
        cr[bl * 2 + q] = (pred == y) ? 1.f : 0.f;
    }
    __syncthreads();

    if (t == 0) {
        float sl = 0.f, scv = 0.f;
        for (int i = 0; i < 8; i++) { sl += ls[i]; scv += cr[i]; }
        g_ploss[blockIdx.x] = sl;
        g_pcorr[blockIdx.x] = scv;
    }
}

// =====================================================================
// Kernel 4: deterministic final reduction
// =====================================================================
__global__ void reduce_kernel(float* __restrict__ out)
{
    __shared__ float sl[128];
    __shared__ float sc_[128];
    int t = threadIdx.x;
    sl[t] = g_ploss[t];
    sc_[t] = g_pcorr[t];
    __syncthreads();
    for (int s = 64; s; s >>= 1) {
        if (t < s) { sl[t] += sl[t + s]; sc_[t] += sc_[t + s]; }
        __syncthreads();
    }
    if (t == 0) {
        float loss = sl[0] * (1.f / 1024.f);
        out[0] = loss;
        out[1] = loss;
        out[2] = 0.f;
        out[3] = sc_[0];
        out[4] = 1024.f;
    }
}

extern "C" void kernel_launch(void* const* d_in, const int* in_sizes, int n_in,
                              void* d_out, int out_size)
{
    const float* sxs = (const float*)d_in[1];
    const float* qxs = (const float*)d_in[2];
    const float* c1w = (const float*)d_in[4];
    const float* c1b = (const float*)d_in[5];
    const float* bn1 = (const float*)d_in[6];
    const float* c2w = (const float*)d_in[7];
    const float* c2b = (const float*)d_in[8];
    const float* bn2 = (const float*)d_in[9];
    const float* c3w = (const float*)d_in[10];
    const float* c3b = (const float*)d_in[11];
    const float* bn3 = (const float*)d_in[12];
    const float* c4w = (const float*)d_in[13];
    const float* c4b = (const float*)d_in[14];
    const float* bn4 = (const float*)d_in[15];
    const float* lin_w = (const float*)d_in[16];
    const float* emb = (const float*)d_in[17];
    const float* w1 = (const float*)d_in[18];
    const float* w2 = (const float*)d_in[19];
    const float* tags = (const float*)d_in[20];
    const float* rq = (const float*)d_in[21];
    const float* rk = (const float*)d_in[22];
    const float* rv = (const float*)d_in[23];
    const float* ro = (const float*)d_in[24];
    const float* lnw = (const float*)d_in[25];
    const float* lnb = (const float*)d_in[26];
    const int* sys = (const int*)d_in[27];
    const int* qys = (const int*)d_in[28];

    const size_t smF = 32294 * sizeof(float);   // 129176 B
    const size_t smL = 20704 * sizeof(float);   // 82816 B
    const size_t smQ = 16128 * sizeof(float);   // 64512 B
    cudaFuncSetAttribute(feat_kernel, cudaFuncAttributeMaxDynamicSharedMemorySize, (int)smF);
    cudaFuncSetAttribute(lor_kernel, cudaFuncAttributeMaxDynamicSharedMemorySize, (int)smL);
    cudaFuncSetAttribute(query_kernel, cudaFuncAttributeMaxDynamicSharedMemorySize, (int)smQ);

    feat_kernel<<<4096, 512, smF>>>(sxs, qxs, c1w, c1b, bn1, c2w, c2b, bn2,
                                    c3w, c3b, bn3, c4w, c4b, bn4, lin_w);
    lor_kernel<<<1536, 512, smL>>>(emb, w1, w2, tags, rq, rk, rv, ro, lnw, lnb, sys);
    query_kernel<<<128, 256, smQ>>>(emb, w1, w2, tags, qys);
    reduce_kernel<<<1, 128>>>((float*)d_out);
}

// round 2
// speedup vs baseline: 1.7292x; 1.7292x over previous
#include <cuda_runtime.h>
#include <math.h>

#define EPSC 1e-5f

// ---- scratch (no allocation allowed) ----
__device__ float g_feats[4096 * 64];      // 3072 support + 1024 query features
__device__ float g_lors[512 * 24 * 64];   // (B, S*4, DIM)
__device__ float g_ploss[128];
__device__ float g_pcorr[128];

__device__ __forceinline__ float gelu_f(float x) {
    return 0.5f * x * (1.0f + erff(x * 0.70710678118654752f));
}

__device__ __forceinline__ void ffma2(unsigned long long& d, unsigned long long a,
                                      unsigned long long b) {
    asm("fma.rn.f32x2 %0, %1, %2, %0;" : "+l"(d) : "l"(a), "l"(b));
}
__device__ __forceinline__ float2 unpk64(unsigned long long v) {
    float2 r; asm("mov.b64 {%0, %1}, %2;" : "=f"(r.x), "=f"(r.y) : "l"(v)); return r;
}

// =====================================================================
// conv 3x3, 32->32 ch, 8x8 interior of 10x10 padded buf, layout [pos*32+ci].
// Thread: lane c = out channel, y = t>>5 = row; computes all 8 x-cells.
// Accumulate in f32x2 over ci-parity; weights pre-paired as u64 in smem:
//   wp[(pair*9 + dy*3+dx)*32 + c] = (w[c][2*pair][k], w[c][2*pair+1][k])
// =====================================================================
__device__ __forceinline__ void conv3x3_f2(
    const float* __restrict__ src, float* __restrict__ dst,
    const unsigned long long* __restrict__ wp,
    const float* __restrict__ A, const float* __restrict__ Bv,
    int c, int y)
{
    unsigned long long acc[8];
#pragma unroll
    for (int x = 0; x < 8; x++) acc[x] = 0ull;

#pragma unroll 1
    for (int quad = 0; quad < 8; quad++) {
#pragma unroll
        for (int dy = 0; dy < 3; dy++) {
            const float* rp = src + (y + dy) * 320 + quad * 4;
            ulonglong2 V[10];
#pragma unroll
            for (int p = 0; p < 10; p++)
                V[p] = *(const ulonglong2*)(rp + p * 32);
#pragma unroll
            for (int k = 0; k < 3; k++) {
                unsigned long long wA = wp[((2 * quad) * 9 + dy * 3 + k) * 32 + c];
                unsigned long long wB = wp[((2 * quad + 1) * 9 + dy * 3 + k) * 32 + c];
#pragma unroll
                for (int x = 0; x < 8; x++) {
                    ffma2(acc[x], V[x + k].x, wA);
                    ffma2(acc[x], V[x + k].y, wB);
                }
            }
        }
    }
    float Ac = A[c], Bc = Bv[c];
#pragma unroll
    for (int x = 0; x < 8; x++) {
        float2 s = unpk64(acc[x]);
        dst[((y + 1) * 10 + (x + 1)) * 32 + c] = gelu_f((s.x + s.y) * Ac + Bc);
    }
}

// =====================================================================
// Kernel 1: feature extractor. 256 threads, 2 images per block, 2 blocks/SM.
// =====================================================================
__global__ __launch_bounds__(256, 2) void feat_kernel(
    const float* __restrict__ sxs, const float* __restrict__ qxs,
    const float* __restrict__ c1w, const float* __restrict__ c1b, const float* __restrict__ bn1,
    const float* __restrict__ c2w, const float* __restrict__ c2b, const float* __restrict__ bn2,
    const float* __restrict__ c3w, const float* __restrict__ c3b, const float* __restrict__ bn3,
    const float* __restrict__ c4w, const float* __restrict__ c4b, const float* __restrict__ bn4,
    const float* __restrict__ lin_w)
{
    extern __shared__ float sm[];
    float* w2p  = sm;             // 9216 (paired u64 view)
    float* w3p  = sm + 9216;      // 9216
    float* buf0 = sm + 18432;     // 3200 (10x10x32, ring stays zero)
    float* buf1 = sm + 21632;     // 3200 (also per-image scratch)
    float* w1s  = sm + 24832;     // 288 [k*32+co]
    float* w4s  = sm + 25120;     // 288 [ci*9+k]
    float* A1   = sm + 25408;     // 32
    float* B1v  = sm + 25440;
    float* A2   = sm + 25472;
    float* B2v  = sm + 25504;
    float* A3   = sm + 25536;
    float* B3v  = sm + 25568;
    float* AB4  = sm + 25600;     // 2
    float* flat = sm + 25602;     // 64
    float* red  = sm + 25668;     // 256
    // total 25924 floats = 103696 B

    const int t = threadIdx.x;
    const int c = t & 31;
    const int y = t >> 5;   // 0..7

    // ---- one-time setup ----
    for (int i = t; i < 9216; i += 256) {
        int parity = i & 1, idx = i >> 1;
        int cc = idx & 31, pk2 = idx >> 5;      // pk2 = pair*9+k, 0..143
        int p = pk2 / 9, k = pk2 - p * 9;
        int gsrc = cc * 288 + (2 * p + parity) * 9 + k;
        w2p[i] = c2w[gsrc];
        w3p[i] = c3w[gsrc];
    }
    for (int i = t; i < 288; i += 256) {
        int co = i / 9, k = i - co * 9;
        w1s[k * 32 + co] = c1w[i];
        w4s[i] = c4w[i];
    }
    for (int i = t; i < 3200; i += 256) buf0[i] = 0.f;
    if (t < 32) {
        float g = bn1[t], bt = bn1[32 + t], m = bn1[64 + t], v = bn1[96 + t];
        float sc = g * rsqrtf(v + EPSC);
        A1[t] = sc * (1.f / 16.f);
        B1v[t] = (c1b[t] - m) * sc + bt;
        g = bn2[t]; bt = bn2[32 + t]; m = bn2[64 + t]; v = bn2[96 + t];
        sc = g * rsqrtf(v + EPSC);
        A2[t] = sc; B2v[t] = (c2b[t] - m) * sc + bt;
        g = bn3[t]; bt = bn3[32 + t]; m = bn3[64 + t]; v = bn3[96 + t];
        sc = g * rsqrtf(v + EPSC);
        A3[t] = sc; B3v[t] = (c3b[t] - m) * sc + bt;
    }
    if (t == 0) {
        float g = bn4[0], bt = bn4[1], m = bn4[2], v = bn4[3];
        float sc = g * rsqrtf(v + EPSC);
        AB4[0] = sc; AB4[1] = (c4b[0] - m) * sc + bt;
    }
    __syncthreads();

    const unsigned long long* w2u = (const unsigned long long*)w2p;
    const unsigned long long* w3u = (const unsigned long long*)w3p;

#pragma unroll 1
    for (int im = 0; im < 2; im++) {
        const int img = blockIdx.x * 2 + im;
        const float* src = (img < 3072) ? (sxs + img * 784) : (qxs + (img - 3072) * 784);

        float* inpad = buf1;          // 900 (30x30 padded image)
        float* rs    = buf1 + 900;    // 720 (horizontal 4-sums)
        float* Ws    = buf1 + 1620;   // 576 (4x4 box sums, [ (3y+dy)*24 + 3x+dx ])

        for (int i = t; i < 900; i += 256) inpad[i] = 0.f;
        __syncthreads();
        for (int i = t; i < 784; i += 256) {
            int yy = i / 28, xx = i - yy * 28;
            inpad[(yy + 1) * 30 + xx + 1] = src[i];
        }
        __syncthreads();

        // separable 4x4 box sums at windows starting (SO[o]+dy, SO[p]+dx)
        {
            const int SO[8] = {0, 3, 7, 10, 14, 17, 21, 24};
            for (int i = t; i < 720; i += 256) {
                int u = i / 24, b3 = i - u * 24;
                int b = SO[b3 / 3] + (b3 % 3);
                const float* ip = inpad + u * 30 + b;
                rs[i] = ip[0] + ip[1] + ip[2] + ip[3];
            }
            __syncthreads();
            for (int i = t; i < 576; i += 256) {
                int a3 = i / 24, b3 = i - a3 * 24;
                int a = SO[a3 / 3] + (a3 % 3);
                Ws[i] = rs[a * 24 + b3] + rs[(a + 1) * 24 + b3]
                      + rs[(a + 2) * 24 + b3] + rs[(a + 3) * 24 + b3];
            }
        }
        __syncthreads();

        // conv1 + pool + bn1 + gelu  (9 FMA per cell via box sums) -> buf0
        {
            float acc[8];
#pragma unroll
            for (int x = 0; x < 8; x++) acc[x] = 0.f;
#pragma unroll
            for (int dy = 0; dy < 3; dy++)
#pragma unroll
                for (int dx = 0; dx < 3; dx++) {
                    float wv = w1s[(dy * 3 + dx) * 32 + c];
#pragma unroll
                    for (int x = 0; x < 8; x++)
                        acc[x] = fmaf(wv, Ws[(3 * y + dy) * 24 + 3 * x + dx], acc[x]);
                }
            float a1 = A1[c], b1 = B1v[c];
#pragma unroll
            for (int x = 0; x < 8; x++)
                buf0[((y + 1) * 10 + x + 1) * 32 + c] = gelu_f(acc[x] * a1 + b1);
        }
        __syncthreads();

        // buf1 was scratch: re-zero fully (conv3 needs a zero ring)
        for (int i = t; i < 3200; i += 256) buf1[i] = 0.f;
        __syncthreads();

        conv3x3_f2(buf0, buf1, w2u, A2, B2v, c, y);   // conv2
        __syncthreads();
        conv3x3_f2(buf1, buf0, w3u, A3, B3v, c, y);   // conv3
        __syncthreads();

        // conv4 (32->1): lane = ci, warp-reduce over channels
        {
            float acc[8];
#pragma unroll
            for (int x = 0; x < 8; x++) acc[x] = 0.f;
#pragma unroll
            for (int dy = 0; dy < 3; dy++)
#pragma unroll
                for (int dx = 0; dx < 3; dx++) {
                    float wv = w4s[c * 9 + dy * 3 + dx];
                    const float* rp = buf0 + ((y + dy) * 10 + dx) * 32 + c;
#pragma unroll
                    for (int x = 0; x < 8; x++)
                        acc[x] = fmaf(wv, rp[x * 32], acc[x]);
                }
#pragma unroll
            for (int x = 0; x < 8; x++) {
                float v = acc[x];
#pragma unroll
                for (int o = 16; o; o >>= 1) v += __shfl_xor_sync(0xffffffffu, v, o);
                acc[x] = v;
            }
            if (c == 0) {
                float s4 = AB4[0], o4 = AB4[1];
#pragma unroll
                for (int x = 0; x < 8; x++)
                    flat[y * 8 + x] = gelu_f(acc[x] * s4 + o4);
            }
        }
        __syncthreads();

        // linear: feat[e] = sum_j flat[j]*lin_w[e][j] ; lin_w streamed from L2
        {
            int e = t & 63, grp = t >> 6, j0 = grp * 16;
            float p = 0.f;
#pragma unroll
            for (int jj = 0; jj < 16; jj += 4) {
                float4 lw = *(const float4*)(lin_w + e * 64 + j0 + jj);
                p = fmaf(lw.x, flat[j0 + jj], p);
                p = fmaf(lw.y, flat[j0 + jj + 1], p);
                p = fmaf(lw.z, flat[j0 + jj + 2], p);
                p = fmaf(lw.w, flat[j0 + jj + 3], p);
            }
            red[grp * 64 + e] = p;
            __syncthreads();
            if (t < 64)
                g_feats[img * 64 + t] = red[t] + red[64 + t] + red[128 + t] + red[192 + t];
        }
        __syncthreads();
    }
}

// =====================================================================
// Kernel 2: LoR adapter on support tokens (B*S*4 = 12288 tokens)
// 8 tokens per block x 64 threads = 512 threads
// =====================================================================
__global__ __launch_bounds__(512) void lor_kernel(
    const float* __restrict__ emb, const float* __restrict__ w1, const float* __restrict__ w2,
    const float* __restrict__ tags, const float* __restrict__ rq, const float* __restrict__ rk,
    const float* __restrict__ rv, const float* __restrict__ ro,
    const float* __restrict__ lnw, const float* __restrict__ lnb,
    const int* __restrict__ sys)
{
    extern __shared__ float sm[];
    float* w1T = sm;             // 4160 [d*65+e]
    float* w2T = w1T + 4160;     // 4160
    float* rqT = w2T + 4160;     // 4160
    float* roS = rqT + 4160;     // 4096
    float* rkT = roS + 4096;     // 1024
    float* rvS = rkT + 1024;     // 1024
    float* xs  = rvS + 1024;     // 512
    float* ahs = xs + 512;       // 512
    float* qvs = ahs + 512;      // 512
    float* lvs = qvs + 512;      // 512
    float* redA = lvs + 512;     // 16
    float* redB = redA + 16;     // 16

    const int t = threadIdx.x;
    for (int i = t; i < 4096; i += 512) {
        int e = i >> 6, d = i & 63;
        w1T[d * 65 + e] = w1[i];
        w2T[d * 65 + e] = w2[i];
        rqT[d * 65 + e] = rq[i];
        roS[i] = ro[i];
    }
    for (int i = t; i < 1024; i += 512) {
        int n = i >> 8, h = (i >> 4) & 15, r = i & 15;
        rkT[i] = rk[(r * 4 + n) * 16 + h];
        rvS[i] = rv[i];
    }
    __syncthreads();

    const int lt = t >> 6;
    const int j = t & 63;
    const int token = blockIdx.x * 8 + lt;
    const int b = token / 24;
    const int k24 = token - b * 24;
    const int s = k24 >> 2;
    const int tg = k24 & 3;

    int cls = sys[b * 6 + s];
    float xv = g_feats[(b * 6 + s) * 64 + j] + emb[cls * 64 + j] + tags[tg * 64 + j];
    xs[t] = xv;
    __syncthreads();

    float h1 = 0.f;
#pragma unroll 8
    for (int d = 0; d < 64; d++) h1 = fmaf(w1T[d * 65 + j], xs[lt * 64 + d], h1);
    ahs[t] = gelu_f(h1);
    __syncthreads();

    float qv = 0.f;
#pragma unroll 8
    for (int d = 0; d < 64; d++) qv = fmaf(w2T[d * 65 + j], ahs[lt * 64 + d], qv);
    qvs[t] = qv;
    __syncthreads();

    float qh = 0.f;
#pragma unroll 8
    for (int d = 0; d < 64; d++) qh = fmaf(rqT[d * 65 + j], qvs[lt * 64 + d], qh);

    const int n = j >> 4;
    const int sub = j & 15;
    float scv = 0.f;
#pragma unroll
    for (int hh = 0; hh < 16; hh++) {
        float qhh = __shfl_sync(0xffffffffu, qh, hh, 16);
        scv = fmaf(qhh, rkT[(n * 16 + hh) * 16 + sub], scv);
    }
    scv *= 0.25f;
    float mx = scv;
    for (int o = 8; o; o >>= 1) mx = fmaxf(mx, __shfl_xor_sync(0xffffffffu, mx, o, 16));
    float ee = expf(scv - mx);
    float ssum = ee;
    for (int o = 8; o; o >>= 1) ssum += __shfl_xor_sync(0xffffffffu, ssum, o, 16);
    float p = ee / ssum;

    float lv = 0.f;
#pragma unroll
    for (int r = 0; r < 16; r++) {
        float pr = __shfl_sync(0xffffffffu, p, r, 16);
        lv = fmaf(pr, rvS[(r * 4 + n) * 16 + sub], lv);
    }
    lvs[t] = lv;
    __syncthreads();

    float outv = 0.f;
#pragma unroll 8
    for (int d = 0; d < 64; d++) outv = fmaf(roS[d * 64 + j], lvs[lt * 64 + d], outv);
    float z = outv + xs[t];

    float sv = z;
    for (int o = 16; o; o >>= 1) sv += __shfl_xor_sync(0xffffffffu, sv, o);
    int wh = (j >> 5);
    if ((j & 31) == 0) redA[lt * 2 + wh] = sv;
    __syncthreads();
    float mean = (redA[lt * 2] + redA[lt * 2 + 1]) * (1.f / 64.f);
    float dz = z - mean;
    float v2 = dz * dz;
    for (int o = 16; o; o >>= 1) v2 += __shfl_xor_sync(0xffffffffu, v2, o);
    if ((j & 31) == 0) redB[lt * 2 + wh] = v2;
    __syncthreads();
    float var = (redB[lt * 2] + redB[lt * 2 + 1]) * (1.f / 64.f);

    g_lors[token * 64 + j] = dz * rsqrtf(var + EPSC) * lnw[j] + lnb[j];
}

// =====================================================================
// Kernel 3: query path. Rank-6 updated weights applied implicitly.
// =====================================================================
__global__ __launch_bounds__(256) void query_kernel(
    const float* __restrict__ emb, const float* __restrict__ w1, const float* __restrict__ w2,
    const float* __restrict__ tags, const int* __restrict__ qys)
{
    extern __shared__ float sm[];
    float* w1T = sm;             // 4160
    float* w2T = w1T + 4160;     // 4160
    float* lorS = w2T + 4160;    // 6144
    float* xq = lorS + 6144;     // 512
    float* ah = xq + 512;        // 512
    float* pd = ah + 512;        // 512
    float* d1 = pd + 512;        // 48
    float* d2 = d1 + 48;         // 48
    float* lg = d2 + 48;         // 16
    float* ls = lg + 16;         // 8
    float* cr = ls + 8;          // 8

    const int t = threadIdx.x;
    for (int i = t; i < 4096; i += 256) {
        int e = i >> 6, d = i & 63;
        w1T[d * 65 + e] = w1[i];
        w2T[d * 65 + e] = w2[i];
    }
    for (int i = t; i < 6144; i += 256) lorS[i] = g_lors[blockIdx.x * 6144 + i];

    const int bl = t >> 6;
    const int e = t & 63;
    const int b = blockIdx.x * 4 + bl;
    for (int q = 0; q < 2; q++)
        xq[(bl * 2 + q) * 64 + e] = g_feats[3072 * 64 + (b * 2 + q) * 64 + e] + tags[4 * 64 + e];
    __syncthreads();

    if (e < 12) {
        int s = e >> 1, q = e & 1;
        const float* r1 = lorS + bl * 1536 + (s * 4 + 1) * 64;
        const float* xx = xq + (bl * 2 + q) * 64;
        float acc = 0.f;
#pragma unroll 8
        for (int d = 0; d < 64; d++) acc = fmaf(r1[d], xx[d], acc);
        d1[bl * 12 + e] = acc;
    }
    __syncthreads();

    for (int q = 0; q < 2; q++) {
        const float* xx = xq + (bl * 2 + q) * 64;
        float acc = 0.f;
#pragma unroll 8
        for (int d = 0; d < 64; d++) acc = fmaf(w1T[d * 65 + e], xx[d], acc);
#pragma unroll
        for (int s = 0; s < 6; s++)
            acc = fmaf(lorS[bl * 1536 + (s * 4 + 0) * 64 + e], d1[bl * 12 + s * 2 + q], acc);
        ah[(bl * 2 + q) * 64 + e] = gelu_f(acc);
    }
    __syncthreads();

    if (e < 12) {
        int s = e >> 1, q = e & 1;
        const float* r2 = lorS + bl * 1536 + (s * 4 + 3) * 64;
        const float* aa = ah + (bl * 2 + q) * 64;
        float acc = 0.f;
#pragma unroll 8
        for (int d = 0; d < 64; d++) acc = fmaf(r2[d], aa[d], acc);
        d2[bl * 12 + e] = acc;
    }
    __syncthreads();

    for (int q = 0; q < 2; q++) {
        const float* aa = ah + (bl * 2 + q) * 64;
        float acc = 0.f;
#pragma unroll 8
        for (int d = 0; d < 64; d++) acc = fmaf(w2T[d * 65 + e], aa[d], acc);
#pragma unroll
        for (int s = 0; s < 6; s++)
            acc = fmaf(lorS[bl * 1536 + (s * 4 + 2) * 64 + e], d2[bl * 12 + s * 2 + q], acc);
        pd[(bl * 2 + q) * 64 + e] = acc;
    }
    __syncthreads();

    if (e < 4) {
        int q = e >> 1, l = e & 1;
        float acc = 0.f;
#pragma unroll 8
        for (int d = 0; d < 64; d++) acc = fmaf(emb[l * 64 + d], pd[(bl * 2 + q) * 64 + d], acc);
        lg[bl * 4 + e] = acc;
    }
    __syncthreads();

    if (e < 2) {
        int q = e;
        float l0 = lg[bl * 4 + q * 2], l1 = lg[bl * 4 + q * 2 + 1];
        int y = qys[b * 2 + q];
        float m = fmaxf(l0, l1);
        float lse = m + logf(expf(l0 - m) + expf(l1 - m));
        ls[bl * 2 + q] = lse - (y ? l1 : l0);
        int pred = (l1 > l0) ? 1 : 0;
        cr[bl * 2 + q] = (pred == y) ? 1.f : 0.f;
    }
    __syncthreads();

    if (t == 0) {
        float sl = 0.f, scv = 0.f;
        for (int i = 0; i < 8; i++) { sl += ls[i]; scv += cr[i]; }
        g_ploss[blockIdx.x] = sl;
        g_pcorr[blockIdx.x] = scv;
    }
}

// =====================================================================
// Kernel 4: deterministic final reduction
// =====================================================================
__global__ void reduce_kernel(float* __restrict__ out)
{
    __shared__ float sl[128];
    __shared__ float sc_[128];
    int t = threadIdx.x;
    sl[t] = g_ploss[t];
    sc_[t] = g_pcorr[t];
    __syncthreads();
    for (int s = 64; s; s >>= 1) {
        if (t < s) { sl[t] += sl[t + s]; sc_[t] += sc_[t + s]; }
        __syncthreads();
    }
    if (t == 0) {
        float loss = sl[0] * (1.f / 1024.f);
        out[0] = loss;
        out[1] = loss;
        out[2] = 0.f;
        out[3] = sc_[0];
        out[4] = 1024.f;
    }
}

extern "C" void kernel_launch(void* const* d_in, const int* in_sizes, int n_in,
                              void* d_out, int out_size)
{
    const float* sxs = (const float*)d_in[1];
    const float* qxs = (const float*)d_in[2];
    const float* c1w = (const float*)d_in[4];
    const float* c1b = (const float*)d_in[5];
    const float* bn1 = (const float*)d_in[6];
    const float* c2w = (const float*)d_in[7];
    const float* c2b = (const float*)d_in[8];
    const float* bn2 = (const float*)d_in[9];
    const float* c3w = (const float*)d_in[10];
    const float* c3b = (const float*)d_in[11];
    const float* bn3 = (const float*)d_in[12];
    const float* c4w = (const float*)d_in[13];
    const float* c4b = (const float*)d_in[14];
    const float* bn4 = (const float*)d_in[15];
    const float* lin_w = (const float*)d_in[16];
    const float* emb = (const float*)d_in[17];
    const float* w1 = (const float*)d_in[18];
    const float* w2 = (const float*)d_in[19];
    const float* tags = (const float*)d_in[20];
    const float* rq = (const float*)d_in[21];
    const float* rk = (const float*)d_in[22];
    const float* rv = (const float*)d_in[23];
    const float* ro = (const float*)d_in[24];
    const float* lnw = (const float*)d_in[25];
    const float* lnb = (const float*)d_in[26];
    const int* sys = (const int*)d_in[27];
    const int* qys = (const int*)d_in[28];

    const size_t smF = 25924 * sizeof(float);   // 103696 B -> 2 blocks/SM
    const size_t smL = 20704 * sizeof(float);   // 82816 B
    const size_t smQ = 16128 * sizeof(float);   // 64512 B
    cudaFuncSetAttribute(feat_kernel, cudaFuncAttributeMaxDynamicSharedMemorySize, (int)smF);
    cudaFuncSetAttribute(lor_kernel, cudaFuncAttributeMaxDynamicSharedMemorySize, (int)smL);
    cudaFuncSetAttribute(query_kernel, cudaFuncAttributeMaxDynamicSharedMemorySize, (int)smQ);

    feat_kernel<<<2048, 256, smF>>>(sxs, qxs, c1w, c1b, bn1, c2w, c2b, bn2,
                                    c3w, c3b, bn3, c4w, c4b, bn4, lin_w);
    lor_kernel<<<1536, 512, smL>>>(emb, w1, w2, tags, rq, rk, rv, ro, lnw, lnb, sys);
    query_kernel<<<128, 256, smQ>>>(emb, w1, w2, tags, qys);
    reduce_kernel<<<1, 128>>>((float*)d_out);
}